// round 11
// baseline (speedup 1.0000x reference)
#include <cuda_runtime.h>
#include <math.h>

#define DT 0.01f
#define TPB     256
#define CHUNK   1024                   // elements per warp
#define NCHUNK  8192                   // 8388608 / 1024
#define GRID1   512                    // k_partial: 8 warps x 2 chunks each
#define GRID3   1024                   // k_final:   8 warps x 1 chunk each
#define WPAD    9                      // staging stride (float2) per lane

// Tuples (A,P,X,V): v' = A*v + V ; x' = x + P*v + X
__device__ float4 g_chunk[NCHUNK];     // per-chunk totals
__device__ float4 g_pref [NCHUNK];     // per-chunk exclusive prefixes

__device__ __forceinline__ float4 comp(float4 f, float4 g) {
    float4 r;
    r.x = g.x * f.x;
    r.y = f.y + g.y * f.x;
    r.z = f.z + g.y * f.w + g.z;
    r.w = g.x * f.w + g.w;
    return r;
}
__device__ __forceinline__ float4 ident() { return make_float4(1.f, 0.f, 0.f, 0.f); }

__device__ __forceinline__ float4 shfl_up4(float4 v, int d, unsigned m) {
    float4 r;
    r.x = __shfl_up_sync(m, v.x, d);
    r.y = __shfl_up_sync(m, v.y, d);
    r.z = __shfl_up_sync(m, v.z, d);
    r.w = __shfl_up_sync(m, v.w, d);
    return r;
}

__device__ __forceinline__ void get_coeffs(const float* mass, const float* fric,
                                           float& alpha, float& beta, float& fb) {
    float m_safe = fabsf(mass[0]) + 0.001f;
    beta  = DT / m_safe;
    fb    = fric[0] * beta;            // = 1 - alpha, no cancellation
    alpha = 1.0f - fb;
}

// ---------------- Pass 1: warp-autonomous chunk tuples, 2 chunks/warp, 1 wave ----------------
__global__ void __launch_bounds__(TPB)
k_partial(const float* __restrict__ act,
          const float* __restrict__ mass,
          const float* __restrict__ fric) {
    int lane = threadIdx.x & 31, wid = threadIdx.x >> 5;

    float alpha, beta, fb;
    get_coeffs(mass, fric, alpha, beta, fb);
    float l2a  = log2f(alpha);
    float w0   = exp2f(l2a * (float)(CHUNK - 1 - 4 * lane));
    float step = exp2f(l2a * -128.0f);
    float ai   = 1.0f / alpha;
    float ai2  = ai * ai;
    float ai3  = ai2 * ai;

    float A = alpha;
    #pragma unroll
    for (int k = 0; k < 10; k++) A *= A;                 // alpha^1024
    float denom = fb;
    if (fabsf(denom) < 1e-12f) denom = 1e-12f;
    float P = DT * alpha * (1.0f - A) / denom;

    #pragma unroll
    for (int half = 0; half < 2; half++) {
        int chunk = blockIdx.x * 8 + wid + half * (NCHUNK / 2);
        const float4* g4 = reinterpret_cast<const float4*>(act) + (size_t)chunk * (CHUNK / 4);

        float4 d[8];                                     // batch: MLP = 8
        #pragma unroll
        for (int r = 0; r < 8; r++) d[r] = g4[r * 32 + lane];

        float w = w0;
        float acc0 = 0.f, acc1 = 0.f, acc2 = 0.f, acc3 = 0.f;
        float s0 = 0.f, s1 = 0.f, s2 = 0.f, s3 = 0.f;
        #pragma unroll
        for (int r = 0; r < 8; r++) {
            acc0 = fmaf(d[r].x, w, acc0);
            acc1 = fmaf(d[r].y, w, acc1);
            acc2 = fmaf(d[r].z, w, acc2);
            acc3 = fmaf(d[r].w, w, acc3);
            s0 += d[r].x; s1 += d[r].y; s2 += d[r].z; s3 += d[r].w;
            w *= step;
        }
        float W = fmaf(ai3, acc3, fmaf(ai2, acc2, fmaf(ai, acc1, acc0)));
        float S = (s0 + s1) + (s2 + s3);
        #pragma unroll
        for (int dd = 16; dd > 0; dd >>= 1) {
            W += __shfl_down_sync(0xffffffffu, W, dd);
            S += __shfl_down_sync(0xffffffffu, S, dd);
        }
        if (lane == 0) {
            float vz = beta * W;
            float xz = DT * (beta * S - alpha * vz) / denom;
            g_chunk[chunk] = make_float4(A, P, xz, vz);
        }
    }
}

// ---------------- Pass 2: scan 8192 chunk tuples -> 8192 exclusive prefixes ----------------
__global__ void __launch_bounds__(1024)
k_blockscan() {
    __shared__ float4 wt[32];
    int tid = threadIdx.x, lane = tid & 31, wid = tid >> 5;

    float4 c[8];
    #pragma unroll
    for (int i = 0; i < 8; i++) c[i] = g_chunk[tid * 8 + i];
    float4 val = c[0];
    #pragma unroll
    for (int i = 1; i < 8; i++) val = comp(val, c[i]);

    #pragma unroll
    for (int d = 1; d < 32; d <<= 1) {
        float4 up = shfl_up4(val, d, 0xffffffffu);
        if (lane >= d) val = comp(up, val);
    }
    if (lane == 31) wt[wid] = val;
    __syncthreads();
    if (wid == 0) {
        float4 cc = wt[lane];
        #pragma unroll
        for (int d = 1; d < 32; d <<= 1) {
            float4 up = shfl_up4(cc, d, 0xffffffffu);
            if (lane >= d) cc = comp(up, cc);
        }
        wt[lane] = cc;
    }
    __syncthreads();
    float4 wexcl = (wid == 0) ? ident() : wt[wid - 1];
    float4 lexcl = shfl_up4(val, 1, 0xffffffffu);
    if (lane == 0) lexcl = ident();
    float4 E = comp(wexcl, lexcl);                       // exclusive @ chunk 8*tid

    #pragma unroll
    for (int i = 0; i < 8; i++) {
        g_pref[tid * 8 + i] = E;
        E = comp(E, c[i]);
    }
}

// ---------------- Pass 3: warp-owned chunks, (X,V)-scan rounds, staged coalesced stores ----------------
__global__ void __launch_bounds__(TPB)
k_final(const float* __restrict__ act,
        const float* __restrict__ initst,
        const float* __restrict__ mass,
        const float* __restrict__ fric,
        float2* __restrict__ out2) {
    __shared__ __align__(16) float2 st[8][32 * WPAD];    // 18432B, per-warp staging
    int lane = threadIdx.x & 31, wid = threadIdx.x >> 5;
    int chunk = blockIdx.x * 8 + wid;

    float alpha, beta, fb;
    get_coeffs(mass, fric, alpha, beta, fb);
    float denom = fb;
    if (fabsf(denom) < 1e-12f) denom = 1e-12f;
    float l2a = log2f(alpha);

    // step constants for the (X,V) scan: at step d, right operand covers 4d elements
    float A4  = alpha * alpha; A4 *= A4;                 // alpha^4
    float As[5], Ps[5];
    As[0] = A4;
    #pragma unroll
    for (int s = 1; s < 5; s++) As[s] = As[s - 1] * As[s - 1];
    #pragma unroll
    for (int s = 0; s < 5; s++) Ps[s] = DT * alpha * (1.0f - As[s]) / denom;
    float A128 = As[4] * As[4];
    float P128 = DT * alpha * (1.0f - A128) / denom;
    // per-lane exclusive homogeneous part: alpha^(4*lane), P(4*lane)
    float Aex = exp2f(l2a * (float)(4 * lane));
    float Pex = DT * alpha * (1.0f - Aex) / denom;

    // chunk incoming state
    float x0 = initst[0];
    float v0 = initst[1];
    float4 e = g_pref[chunk];
    float vv = e.x * v0 + e.w;
    float xx = x0 + e.y * v0 + e.z;

    if (chunk == 0 && lane == 0) out2[0] = make_float2(x0, v0);

    const float4* g4 = reinterpret_cast<const float4*>(act) + (size_t)chunk * (CHUNK / 4);
    float2* ob = out2 + 1 + (size_t)chunk * CHUNK;
    float2* sw = st[wid];

    #pragma unroll
    for (int r = 0; r < 8; r++) {
        float4 a = g4[r * 32 + lane];                    // L2-resident after pass 1

        // own 4-element zero-state (X,V)
        float V = beta * a.x;            float X = DT * V;
        V = fmaf(alpha, V, beta * a.y);  X = fmaf(DT, V, X);
        V = fmaf(alpha, V, beta * a.z);  X = fmaf(DT, V, X);
        V = fmaf(alpha, V, beta * a.w);  X = fmaf(DT, V, X);

        // inclusive warp scan of (X,V) with analytic (A,P) per step
        #pragma unroll
        for (int s = 0; s < 5; s++) {
            int dd = 1 << s;
            float Xu = __shfl_up_sync(0xffffffffu, X, dd);
            float Vu = __shfl_up_sync(0xffffffffu, V, dd);
            if (lane >= dd) {
                X = fmaf(Ps[s], Vu, X) + Xu;
                V = fmaf(As[s], Vu, V);
            }
        }
        // round total (lane 31 inclusive)
        float Xt = __shfl_sync(0xffffffffu, X, 31);
        float Vt = __shfl_sync(0xffffffffu, V, 31);
        // exclusive per lane
        float Xe = __shfl_up_sync(0xffffffffu, X, 1);
        float Ve = __shfl_up_sync(0xffffffffu, V, 1);
        if (lane == 0) { Xe = 0.f; Ve = 0.f; }

        // lane start state = exclusive tuple applied to round-start state
        float vl = fmaf(Aex, vv, Ve);
        float xl = fmaf(Pex, vv, xx) + Xe;

        // replay 4 elements, stage into padded smem
        float2* so = sw + lane * WPAD;
        vl = fmaf(alpha, vl, beta * a.x); xl = fmaf(DT, vl, xl); so[0] = make_float2(xl, vl);
        vl = fmaf(alpha, vl, beta * a.y); xl = fmaf(DT, vl, xl); so[1] = make_float2(xl, vl);
        vl = fmaf(alpha, vl, beta * a.z); xl = fmaf(DT, vl, xl); so[2] = make_float2(xl, vl);
        vl = fmaf(alpha, vl, beta * a.w); xl = fmaf(DT, vl, xl); so[3] = make_float2(xl, vl);

        // advance round-start state (xx uses old vv)
        xx = fmaf(P128, vv, xx) + Xt;
        vv = fmaf(A128, vv, Vt);

        __syncwarp();
        // coalesced store of the 128 staged float2
        #pragma unroll
        for (int j = 0; j < 4; j++) {
            int m = 32 * j + lane;                       // element index within round
            float2 vsm = sw[(m >> 2) * WPAD + (m & 3)];
            ob[128 * r + m] = vsm;
        }
        __syncwarp();
    }
}

extern "C" void kernel_launch(void* const* d_in, const int* in_sizes, int n_in,
                              void* d_out, int out_size) {
    const float* init = (const float*)d_in[0];
    const float* act  = (const float*)d_in[1];
    const float* mass = (const float*)d_in[2];
    const float* fric = (const float*)d_in[3];
    float2* out2 = (float2*)d_out;

    k_partial<<<GRID1, TPB>>>(act, mass, fric);
    k_blockscan<<<1, 1024>>>();
    k_final<<<GRID3, TPB>>>(act, init, mass, fric, out2);
}

// round 12
// speedup vs baseline: 1.1992x; 1.1992x over previous
#include <cuda_runtime.h>
#include <math.h>

#define DT 0.01f
#define SEG    32                      // actions per thread (k_final)
#define TPB    256
#define NTILE  1024                    // 8388608 / 8192
#define TILE   (TPB * SEG)             // 8192 floats per tile
#define SSTR   36                      // padded smem stride (floats) per segment
#define GRID1  512                     // k_partial blocks (2 tiles each)

// Per-tile affine tuples. (A,P,X,V): v' = A*v + V ; x' = x + P*v + X
// After k_partial (incl. fused last-block scan): EXCLUSIVE PREFIXES.
__device__ float4 g_blk[NTILE];
__device__ unsigned int g_done;        // monotone across replays

__device__ __forceinline__ float4 comp(float4 f, float4 g) {
    float4 r;
    r.x = g.x * f.x;
    r.y = f.y + g.y * f.x;
    r.z = f.z + g.y * f.w + g.z;
    r.w = g.x * f.w + g.w;
    return r;
}
__device__ __forceinline__ float4 ident() { return make_float4(1.f, 0.f, 0.f, 0.f); }

__device__ __forceinline__ float4 shfl_up4(float4 v, int d, unsigned m) {
    float4 r;
    r.x = __shfl_up_sync(m, v.x, d);
    r.y = __shfl_up_sync(m, v.y, d);
    r.z = __shfl_up_sync(m, v.z, d);
    r.w = __shfl_up_sync(m, v.w, d);
    return r;
}

__device__ __forceinline__ void get_coeffs(const float* mass, const float* fric,
                                           float& alpha, float& beta, float& fb) {
    float m_safe = fabsf(mass[0]) + 0.001f;
    beta  = DT / m_safe;
    fb    = fric[0] * beta;            // = 1 - alpha, no cancellation
    alpha = 1.0f - fb;
}

// ---------------- Pass 1: 2 tile tuples per block + fused last-block scan ----------------
__global__ void __launch_bounds__(TPB)
k_partial(const float* __restrict__ act,
          const float* __restrict__ mass,
          const float* __restrict__ fric) {
    __shared__ float2 wred[2][TPB / 32];
    __shared__ float4 wtot[TPB / 32];
    __shared__ int s_last;
    int tid = threadIdx.x, lane = tid & 31, wid = tid >> 5;

    float alpha, beta, fb;
    get_coeffs(mass, fric, alpha, beta, fb);
    float l2a  = log2f(alpha);
    float w0   = exp2f(l2a * (float)(8191 - 4 * tid));
    float step = exp2f(l2a * -1024.0f);
    float ai   = 1.0f / alpha;
    float ai2  = ai * ai;
    float ai3  = ai2 * ai;
    float denom = fb;
    if (fabsf(denom) < 1e-12f) denom = 1e-12f;
    float Abig = alpha;
    #pragma unroll
    for (int j = 0; j < 13; j++) Abig *= Abig;           // alpha^8192
    float Pbig = DT * alpha * (1.0f - Abig) / denom;

    #pragma unroll
    for (int half = 0; half < 2; half++) {
        int tile = blockIdx.x + half * GRID1;
        const float4* g4 = reinterpret_cast<const float4*>(act) + (size_t)tile * (TILE / 4);

        float4 d[8];                                     // batch: MLP = 8
        #pragma unroll
        for (int r = 0; r < 8; r++) d[r] = g4[r * TPB + tid];

        float w = w0;
        float acc0 = 0.f, acc1 = 0.f, acc2 = 0.f, acc3 = 0.f;
        float s0 = 0.f, s1 = 0.f, s2 = 0.f, s3 = 0.f;
        #pragma unroll
        for (int r = 0; r < 8; r++) {
            acc0 = fmaf(d[r].x, w, acc0);
            acc1 = fmaf(d[r].y, w, acc1);
            acc2 = fmaf(d[r].z, w, acc2);
            acc3 = fmaf(d[r].w, w, acc3);
            s0 += d[r].x; s1 += d[r].y; s2 += d[r].z; s3 += d[r].w;
            w *= step;
        }
        float W = fmaf(ai3, acc3, fmaf(ai2, acc2, fmaf(ai, acc1, acc0)));
        float S = (s0 + s1) + (s2 + s3);
        #pragma unroll
        for (int dd = 16; dd > 0; dd >>= 1) {
            W += __shfl_down_sync(0xffffffffu, W, dd);
            S += __shfl_down_sync(0xffffffffu, S, dd);
        }
        if (lane == 0) wred[half][wid] = make_float2(S, W);
    }
    __syncthreads();
    if (tid < 2) {                                       // one finalizer thread per tile
        float St = 0.f, Wt = 0.f;
        #pragma unroll
        for (int i = 0; i < TPB / 32; i++) { St += wred[tid][i].x; Wt += wred[tid][i].y; }
        float vz = beta * Wt;
        float xz = DT * (beta * St - alpha * vz) / denom;
        g_blk[blockIdx.x + tid * GRID1] = make_float4(Abig, Pbig, xz, vz);
    }
    __syncthreads();
    if (tid == 0) {
        __threadfence();
        unsigned int old = atomicAdd(&g_done, 1u);
        s_last = (((old + 1u) & (GRID1 - 1u)) == 0u);    // monotone: replay-safe
    }
    __syncthreads();

    // Last arriving block converts g_blk totals -> exclusive prefixes in place.
    if (s_last) {
        __threadfence();
        float4 t0 = g_blk[4 * tid + 0];
        float4 t1 = g_blk[4 * tid + 1];
        float4 t2 = g_blk[4 * tid + 2];
        float4 t3 = g_blk[4 * tid + 3];
        float4 acc = comp(comp(comp(t0, t1), t2), t3);
        #pragma unroll
        for (int dd = 1; dd < 32; dd <<= 1) {
            float4 up = shfl_up4(acc, dd, 0xffffffffu);
            if (lane >= dd) acc = comp(up, acc);
        }
        if (lane == 31) wtot[wid] = acc;
        __syncthreads();
        if (tid < TPB / 32) {
            float4 c = wtot[tid];
            #pragma unroll
            for (int dd = 1; dd < TPB / 32; dd <<= 1) {
                float4 up = shfl_up4(c, dd, 0xffu);
                if (tid >= dd) c = comp(up, c);
            }
            wtot[tid] = c;
        }
        __syncthreads();
        float4 wexcl = (wid == 0) ? ident() : wtot[wid - 1];
        float4 lexcl = shfl_up4(acc, 1, 0xffffffffu);
        if (lane == 0) lexcl = ident();
        float4 E = comp(wexcl, lexcl);
        g_blk[4 * tid + 0] = E;
        E = comp(E, t0); g_blk[4 * tid + 1] = E;
        E = comp(E, t1); g_blk[4 * tid + 2] = E;
        E = comp(E, t2); g_blk[4 * tid + 3] = E;
    }
}

// ---------------- Pass 2: R9 k_final (proven): closed-form tuples + scan + quarter replay ----------------
__global__ void __launch_bounds__(TPB)
k_final(const float* __restrict__ act,
        const float* __restrict__ initst,
        const float* __restrict__ mass,
        const float* __restrict__ fric,
        float2* __restrict__ out2) {
    __shared__ __align__(16) float s[TPB * SSTR];
    __shared__ __align__(16) float2 sout[64 * (SEG + 1)];
    __shared__ float4 wtot[TPB / 32];
    int tid = threadIdx.x, lane = tid & 31, wid = tid >> 5;
    int bid = blockIdx.x;

    {
        const float4* g4 = reinterpret_cast<const float4*>(act) + (size_t)bid * (TILE / 4);
        #pragma unroll
        for (int r = 0; r < TILE / 4 / TPB; r++) {
            int i4 = tid + TPB * r;
            float4 v = g4[i4];
            *reinterpret_cast<float4*>(&s[(i4 >> 3) * SSTR + (i4 & 7) * 4]) = v;
        }
    }
    __syncthreads();

    float alpha, beta, fb;
    get_coeffs(mass, fric, alpha, beta, fb);
    float a2  = alpha * alpha;
    float a4  = a2 * a2;
    float a8  = a4 * a4;
    float a16 = a8 * a8;
    float A   = a16 * a16;                               // alpha^32
    float a31 = a16 * a8 * a4 * a2 * alpha;              // alpha^31
    float denom = fb;
    if (fabsf(denom) < 1e-12f) denom = 1e-12f;
    float Pc = DT * alpha * (1.0f - A) / denom;
    float ai  = 1.0f / alpha;
    float ai2 = ai * ai;
    float ai4 = ai2 * ai2;

    const float* my = s + tid * SSTR;
    float acc0 = 0.f, acc1 = 0.f, acc2 = 0.f, acc3 = 0.f;
    float s0 = 0.f, s1 = 0.f, s2 = 0.f, s3 = 0.f;
    float w = a31;
    #pragma unroll
    for (int j = 0; j < SEG / 4; j++) {
        float4 a = *reinterpret_cast<const float4*>(my + 4 * j);
        acc0 = fmaf(a.x, w, acc0);
        acc1 = fmaf(a.y, w, acc1);
        acc2 = fmaf(a.z, w, acc2);
        acc3 = fmaf(a.w, w, acc3);
        s0 += a.x; s1 += a.y; s2 += a.z; s3 += a.w;
        w *= ai4;
    }
    float W = fmaf(ai2 * ai, acc3, fmaf(ai2, acc2, fmaf(ai, acc1, acc0)));
    float S = (s0 + s1) + (s2 + s3);
    float vz = beta * W;
    float xz = DT * (beta * S - alpha * vz) / denom;

    float4 val = make_float4(A, Pc, xz, vz);
    #pragma unroll
    for (int dd = 1; dd < 32; dd <<= 1) {
        float4 up = shfl_up4(val, dd, 0xffffffffu);
        if (lane >= dd) val = comp(up, val);
    }
    if (lane == 31) wtot[wid] = val;
    __syncthreads();
    if (tid < TPB / 32) {
        float4 c = wtot[tid];
        #pragma unroll
        for (int dd = 1; dd < TPB / 32; dd <<= 1) {
            float4 up = shfl_up4(c, dd, 0xffu);
            if (tid >= dd) c = comp(up, c);
        }
        wtot[tid] = c;
    }
    __syncthreads();
    float4 wexcl = (wid == 0) ? ident() : wtot[wid - 1];
    float4 lexcl = shfl_up4(val, 1, 0xffffffffu);
    if (lane == 0) lexcl = ident();
    float4 e = comp(g_blk[bid], comp(wexcl, lexcl));

    float x0 = initst[0];
    float v0 = initst[1];
    float vin = e.x * v0 + e.w;
    float xin = x0 + e.y * v0 + e.z;

    if (bid == 0 && tid == 0) out2[0] = make_float2(x0, v0);

    float2* out_base = out2 + 1 + (size_t)bid * TILE;
    #pragma unroll
    for (int q = 0; q < 4; q++) {
        if ((tid >> 6) == q) {
            int t = tid & 63;
            float vv = vin, xx = xin;
            float2* so = sout + t * (SEG + 1);
            #pragma unroll
            for (int j = 0; j < SEG / 4; j++) {
                float4 a = *reinterpret_cast<const float4*>(my + 4 * j);
                vv = alpha * vv + beta * a.x; xx += DT * vv; so[4 * j + 0] = make_float2(xx, vv);
                vv = alpha * vv + beta * a.y; xx += DT * vv; so[4 * j + 1] = make_float2(xx, vv);
                vv = alpha * vv + beta * a.z; xx += DT * vv; so[4 * j + 2] = make_float2(xx, vv);
                vv = alpha * vv + beta * a.w; xx += DT * vv; so[4 * j + 3] = make_float2(xx, vv);
            }
        }
        __syncthreads();
        float2* gdst = out_base + q * (64 * SEG);
        #pragma unroll
        for (int w2 = 0; w2 < (64 * SEG) / TPB; w2++) {
            int i2 = tid + TPB * w2;
            gdst[i2] = sout[(i2 >> 5) * (SEG + 1) + (i2 & 31)];
        }
        __syncthreads();
    }
}

extern "C" void kernel_launch(void* const* d_in, const int* in_sizes, int n_in,
                              void* d_out, int out_size) {
    const float* init = (const float*)d_in[0];
    const float* act  = (const float*)d_in[1];
    const float* mass = (const float*)d_in[2];
    const float* fric = (const float*)d_in[3];
    float2* out2 = (float2*)d_out;

    k_partial<<<GRID1, TPB>>>(act, mass, fric);
    k_final<<<NTILE, TPB>>>(act, init, mass, fric, out2);
}